// round 15
// baseline (speedup 1.0000x reference)
#include <cuda_runtime.h>
#include <cuda_bf16.h>
#include <math.h>
#include <stdint.h>

// ---------------------------------------------------------------------------
// GAT pipeline (R14 + gemm BM=128/512thr: half the B staging + L2 traffic).
// Big GEMM: mma.sync bf16 split-precision, cp.async double-buffered B +
// register-prefetched A. CSR build on forked stream. Single-pass gathers.
// Colsum on side stream overlapped with gather1/gemm2.
// ---------------------------------------------------------------------------

#define NN   50000
#define EE   500000
#define KDIM 512
#define HID  128
#define DOUT 20
#define NB_SCAN 98            // ceil(NN/512)

#define NSTEPS 32             // 512 / 16 k-steps
#define NTILES 20             // 160 / 8 n-tiles
#define BFRAG_CNT (NSTEPS * NTILES * 32)   // B fragment table entries (uint4)

// gemm tiling: BM=128, BN=160, chunk K=64 (4 k-steps), 512 threads = 16 warps
#define CH_STEPS 4
#define NCHUNKS 8
// smem layout (bytes)
#define OFF_AF_H 0
#define OFF_AF_L 16384
#define OFF_B0   32768
#define OFF_B1   (OFF_B0 + 40960)
#define SMEM_SZ  (OFF_B1 + 40960)          // 114688

// ------------------------- device scratch ---------------------------------
__device__ __align__(16) float g_Wt2[HID * 24];     // layer-2 B, [k][c]
__device__ __align__(16) uint4 g_Bf[BFRAG_CNT];     // B fragments {bh.xy, bl.xy}
__device__ __align__(16) float g_xl1[NN * HID];
__device__ __align__(16) float g_agg1[NN * HID];
__device__ __align__(16) float g_s0[NN * DOUT];
__device__ float g_el1[NN], g_er1[NN];
__device__ __align__(16) float g_xl2[NN * DOUT];
__device__ float g_el2[NN], g_er2[NN];
__device__ float g_colsum0[DOUT];
__device__ int g_is64;
// CSR
__device__ int g_deg[NN];
__device__ int g_rowoff[NN + 1];
__device__ int g_cursor[NN];
__device__ int g_bsum[NB_SCAN];
__device__ int g_boff[NB_SCAN];
__device__ int g_csrc[EE];

// ------------------------- helpers ----------------------------------------
__device__ __forceinline__ float eluf(float x) {
    return x > 0.f ? x : expm1f(x);
}
__device__ __forceinline__ float leaky(float x) {
    return x > 0.f ? x : 0.2f * x;
}
__device__ __forceinline__ uint32_t packbf(float a, float b) {
    uint32_t r;
    asm("cvt.rn.bf16x2.f32 %0, %1, %2;" : "=r"(r) : "f"(b), "f"(a));
    return r;
}
__device__ __forceinline__ float bflo(float v) {
    __nv_bfloat16 h = __float2bfloat16(v);
    return v - __bfloat162float(h);
}
__device__ __forceinline__ uint32_t smem_u32(const void* p) {
    uint32_t a;
    asm("{ .reg .u64 t; cvta.to.shared.u64 t, %1; cvt.u32.u64 %0, t; }"
        : "=r"(a) : "l"(p));
    return a;
}
__device__ __forceinline__ void cp_async16(uint32_t saddr, const void* g) {
    asm volatile(
        "{ .reg .u64 t; cvta.to.global.u64 t, %1;"
        "  cp.async.cg.shared.global [%0], [t], 16; }"
        :: "r"(saddr), "l"(g) : "memory");
}
__device__ __forceinline__ void mma_bf16(float& c0, float& c1, float& c2, float& c3,
                                         uint32_t a0, uint32_t a1, uint32_t a2, uint32_t a3,
                                         uint32_t b0, uint32_t b1) {
    asm volatile(
        "mma.sync.aligned.m16n8k16.row.col.f32.bf16.bf16.f32 "
        "{%0,%1,%2,%3}, {%4,%5,%6,%7}, {%8,%9}, {%0,%1,%2,%3};"
        : "+f"(c0), "+f"(c1), "+f"(c2), "+f"(c3)
        : "r"(a0), "r"(a1), "r"(a2), "r"(a3), "r"(b0), "r"(b1));
}

// ------------------------- dtype detection + deg zero (side stream) --------
__global__ void detect_kernel(const void* ei) {
    int i = blockIdx.x * blockDim.x + threadIdx.x;
    if (i < NN) g_deg[i] = 0;
    if (i == 0) {
        const long long* p = (const long long*)ei;
        int ok64 = 1;
        for (int k = 0; k < 64; k++) {
            long long v = p[k];
            if (v < 0 || v >= NN) { ok64 = 0; break; }
        }
        g_is64 = ok64;
    }
}
__device__ __forceinline__ int edge_at(const void* ei, int idx) {
    if (g_is64) return (int)((const long long*)ei)[idx];
    return ((const int*)ei)[idx];
}

// ------------------------- prep (fused fragment build) ---------------------
__global__ void prep_kernel(const float* __restrict__ W0,
                            const float* __restrict__ Wl1, const float* __restrict__ Wr1,
                            const float* __restrict__ al1, const float* __restrict__ ar1,
                            const float* __restrict__ Wl2, const float* __restrict__ Wr2,
                            const float* __restrict__ al2, const float* __restrict__ ar2) {
    __shared__ float col[KDIM];
    int b = blockIdx.x;
    int t = threadIdx.x;  // 0..511

    if (b < 160) {
        float v;
        if (b < 128) {
            v = Wl1[b * KDIM + t];
        } else if (b < 148) {
            v = W0[(b - 128) * KDIM + t];
        } else if (b == 148) {
            float s = 0.f;
            for (int h = 0; h < HID; h++) s += Wl1[h * KDIM + t] * al1[h];
            v = s;
        } else if (b == 149) {
            float s = 0.f;
            for (int h = 0; h < HID; h++) s += Wr1[h * KDIM + t] * ar1[h];
            v = s;
        } else {
            v = 0.f;
        }
        col[t] = v;
        __syncthreads();
        if (t < 128) {
            int s = t >> 2;          // k-step 0..31
            int q = t & 3;
            int k = s * 16 + 2 * q;
            float v0 = col[k];
            float v1 = col[k + 1];
            float v2 = col[k + 8];
            float v3 = col[k + 9];
            int tile = b >> 3;
            int lane = ((b & 7) << 2) | q;
            int f = (s * NTILES + tile) * 32 + lane;
            g_Bf[f] = make_uint4(packbf(v0, v1), packbf(v2, v3),
                                 packbf(bflo(v0), bflo(v1)), packbf(bflo(v2), bflo(v3)));
        }
    } else {
        if (t < HID) {
            for (int c = 0; c < DOUT; c++) g_Wt2[t * 24 + c] = Wl2[c * HID + t];
            float s = 0.f;
            for (int h = 0; h < DOUT; h++) s += Wl2[h * HID + t] * al2[h];
            g_Wt2[t * 24 + 20] = s;
            s = 0.f;
            for (int h = 0; h < DOUT; h++) s += Wr2[h * HID + t] * ar2[h];
            g_Wt2[t * 24 + 21] = s;
            g_Wt2[t * 24 + 22] = 0.f;
            g_Wt2[t * 24 + 23] = 0.f;
        } else if (t < 128 + DOUT) {
            g_colsum0[t - 128] = 0.f;
        }
    }
}

// ------------------------- mma.sync big GEMM (BM=128, 512 thr) -------------
__global__ void __launch_bounds__(512, 1) gemm_mma(const float* __restrict__ x) {
    extern __shared__ __align__(16) char sm[];
    uint32_t sb = smem_u32(sm);
    int tid = threadIdx.x;
    int wid = tid >> 5;
    int lane = tid & 31;
    int mw = wid >> 2;          // 0..3
    int nw = wid & 3;           // 0..3
    int g = lane >> 2, q = lane & 3;
    int rowBase = blockIdx.x * 128;

    int rA[4]; int c4A[4]; bool okA[4];
#pragma unroll
    for (int i = 0; i < 4; i++) {
        int idx = tid + i * 512;     // 0..2047
        rA[i] = idx >> 4;            // 0..127
        c4A[i] = idx & 15;
        okA[i] = (rowBase + rA[i]) < NN;
    }

    float acc[2][5][4];
#pragma unroll
    for (int i = 0; i < 2; i++)
#pragma unroll
        for (int j = 0; j < 5; j++)
#pragma unroll
            for (int k = 0; k < 4; k++) acc[i][j][k] = 0.f;

    float4 areg[4];
#pragma unroll
    for (int i = 0; i < 4; i++) {
        areg[i] = make_float4(0.f, 0.f, 0.f, 0.f);
        if (okA[i])
            areg[i] = *(const float4*)(x + (size_t)(rowBase + rA[i]) * KDIM + c4A[i] * 4);
    }
#pragma unroll
    for (int i = 0; i < 5; i++) {
        int s = tid + i * 512;       // 0..2559
        cp_async16(sb + OFF_B0 + s * 16, g_Bf + s);
    }
    asm volatile("cp.async.commit_group;" ::: "memory");

    for (int ch = 0; ch < NCHUNKS; ch++) {
#pragma unroll
        for (int i = 0; i < 4; i++) {
            float4 v = areg[i];
            uint32_t h0 = packbf(v.x, v.y);
            uint32_t h1 = packbf(v.z, v.w);
            uint32_t l0 = packbf(bflo(v.x), bflo(v.y));
            uint32_t l1 = packbf(bflo(v.z), bflo(v.w));
            int r = rA[i];
            int p0 = 2 * c4A[i];
            int s = p0 >> 3;
            int j = (((p0 >> 2) & 1) << 1) | ((r >> 3) & 1);
            int lane0 = ((r & 7) << 2) | (p0 & 3);
            int mt = r >> 4;             // 0..7
            int base = ((s * 8 + mt) * 32) * 16 + j * 4;
            *(uint32_t*)(sm + OFF_AF_H + base + lane0 * 16) = h0;
            *(uint32_t*)(sm + OFF_AF_H + base + (lane0 + 1) * 16) = h1;
            *(uint32_t*)(sm + OFF_AF_L + base + lane0 * 16) = l0;
            *(uint32_t*)(sm + OFF_AF_L + base + (lane0 + 1) * 16) = l1;
        }
        float4 anext[4];
#pragma unroll
        for (int i = 0; i < 4; i++) anext[i] = make_float4(0.f, 0.f, 0.f, 0.f);
        if (ch < NCHUNKS - 1) {
            int k0n = (ch + 1) * 64;
#pragma unroll
            for (int i = 0; i < 4; i++) {
                if (okA[i])
                    anext[i] = *(const float4*)(x + (size_t)(rowBase + rA[i]) * KDIM
                                                + k0n + c4A[i] * 4);
            }
            uint32_t dstB = sb + (((ch + 1) & 1) ? OFF_B1 : OFF_B0);
            const uint4* srcB = g_Bf + (ch + 1) * (CH_STEPS * NTILES * 32);
#pragma unroll
            for (int i = 0; i < 5; i++) {
                int s = tid + i * 512;
                cp_async16(dstB + s * 16, srcB + s);
            }
            asm volatile("cp.async.commit_group;" ::: "memory");
            asm volatile("cp.async.wait_group 1;" ::: "memory");
        } else {
            asm volatile("cp.async.wait_group 0;" ::: "memory");
        }
        __syncthreads();

        int offB = (ch & 1) ? OFF_B1 : OFF_B0;
#pragma unroll
        for (int s = 0; s < CH_STEPS; s++) {
            uint4 ah[2], al[2];
#pragma unroll
            for (int mt = 0; mt < 2; mt++) {
                int tile = s * 8 + mw * 2 + mt;
                ah[mt] = *(uint4*)(sm + OFF_AF_H + (tile * 32 + lane) * 16);
                al[mt] = *(uint4*)(sm + OFF_AF_L + (tile * 32 + lane) * 16);
            }
#pragma unroll
            for (int nt = 0; nt < 5; nt++) {
                int fi = (s * NTILES + nw * 5 + nt) * 32 + lane;
                uint4 bb = *(uint4*)(sm + offB + fi * 16);
#pragma unroll
                for (int mt = 0; mt < 2; mt++) {
                    mma_bf16(acc[mt][nt][0], acc[mt][nt][1], acc[mt][nt][2], acc[mt][nt][3],
                             ah[mt].x, ah[mt].y, ah[mt].z, ah[mt].w, bb.x, bb.y);
                    mma_bf16(acc[mt][nt][0], acc[mt][nt][1], acc[mt][nt][2], acc[mt][nt][3],
                             ah[mt].x, ah[mt].y, ah[mt].z, ah[mt].w, bb.z, bb.w);
                    mma_bf16(acc[mt][nt][0], acc[mt][nt][1], acc[mt][nt][2], acc[mt][nt][3],
                             al[mt].x, al[mt].y, al[mt].z, al[mt].w, bb.x, bb.y);
                }
            }
        }
        __syncthreads();
#pragma unroll
        for (int i = 0; i < 4; i++) areg[i] = anext[i];
    }

#pragma unroll
    for (int mt = 0; mt < 2; mt++) {
#pragma unroll
        for (int half = 0; half < 2; half++) {
            int row = rowBase + (mw * 2 + mt) * 16 + half * 8 + g;
            if (row >= NN) continue;
#pragma unroll
            for (int nt = 0; nt < 5; nt++) {
                int col = nw * 40 + nt * 8 + 2 * q;
                float c0 = acc[mt][nt][half * 2 + 0];
                float c1 = acc[mt][nt][half * 2 + 1];
                if (col < HID) {
                    *(float2*)&g_xl1[(size_t)row * HID + col] = make_float2(c0, c1);
                } else {
                    int cc = col - HID;
                    if (cc < DOUT) {
                        *(float2*)&g_s0[(size_t)row * DOUT + cc] = make_float2(c0, c1);
                    } else if (cc == DOUT) {
                        g_el1[row] = c0;
                        g_er1[row] = c1;
                    }
                }
            }
        }
    }
}

// ------------------------- column-softmax reduce ---------------------------
__global__ void colsum_kernel(const float* __restrict__ b0) {
    __shared__ float bs[DOUT];
    int tid = threadIdx.x;
    if (tid < DOUT) bs[tid] = 0.f;
    __syncthreads();
    float ls[DOUT];
#pragma unroll
    for (int c = 0; c < DOUT; c++) ls[c] = 0.f;
    for (int n = blockIdx.x * blockDim.x + tid; n < NN; n += gridDim.x * blockDim.x) {
#pragma unroll
        for (int c = 0; c < DOUT; c++) ls[c] += expf(g_s0[n * DOUT + c] + b0[c]);
    }
#pragma unroll
    for (int c = 0; c < DOUT; c++) {
#pragma unroll
        for (int off = 16; off; off >>= 1)
            ls[c] += __shfl_xor_sync(0xffffffffu, ls[c], off);
    }
    if ((tid & 31) == 0) {
#pragma unroll
        for (int c = 0; c < DOUT; c++) atomicAdd(&bs[c], ls[c]);
    }
    __syncthreads();
    if (tid < DOUT) atomicAdd(&g_colsum0[tid], bs[tid]);
}

// ------------------------- CSR build (side stream) -------------------------
__global__ void deg_count(const void* __restrict__ ei) {
    int i = blockIdx.x * blockDim.x + threadIdx.x;
    if (i >= EE) return;
    int d = edge_at(ei, EE + i);
    atomicAdd(&g_deg[d], 1);
}

__global__ void scanA_kernel() {
    __shared__ int warpsum[16];
    int b = blockIdx.x, t = threadIdx.x;
    int i = b * 512 + t;
    int v = (i < NN) ? g_deg[i] : 0;
    int x = v;
#pragma unroll
    for (int off = 1; off < 32; off <<= 1) {
        int y = __shfl_up_sync(0xffffffffu, x, off);
        if ((t & 31) >= off) x += y;
    }
    if ((t & 31) == 31) warpsum[t >> 5] = x;
    __syncthreads();
    if (t < 16) {
        int s = warpsum[t];
#pragma unroll
        for (int off = 1; off < 16; off <<= 1) {
            int y = __shfl_up_sync(0xffffu, s, off);
            if (t >= off) s += y;
        }
        warpsum[t] = s;
    }
    __syncthreads();
    int incl = x + ((t >> 5) ? warpsum[(t >> 5) - 1] : 0);
    if (i < NN) g_rowoff[i] = incl - v;
    if (t == 511) g_bsum[b] = incl;
}

__global__ void scanB_kernel() {
    __shared__ int warpsum[4];
    int t = threadIdx.x;
    int v = (t < NB_SCAN) ? g_bsum[t] : 0;
    int x = v;
#pragma unroll
    for (int off = 1; off < 32; off <<= 1) {
        int y = __shfl_up_sync(0xffffffffu, x, off);
        if ((t & 31) >= off) x += y;
    }
    if ((t & 31) == 31) warpsum[t >> 5] = x;
    __syncthreads();
    if (t < 4) {
        int s = warpsum[t];
#pragma unroll
        for (int off = 1; off < 4; off <<= 1) {
            int y = __shfl_up_sync(0xfu, s, off);
            if (t >= off) s += y;
        }
        warpsum[t] = s;
    }
    __syncthreads();
    int incl = x + ((t >> 5) ? warpsum[(t >> 5) - 1] : 0);
    if (t < NB_SCAN) g_boff[t] = incl - v;
}

__global__ void scanC_kernel() {
    int b = blockIdx.x, t = threadIdx.x;
    int i = b * 512 + t;
    if (i < NN) {
        int o = g_rowoff[i] + g_boff[b];
        g_rowoff[i] = o;
        g_cursor[i] = o;
    }
    if (b == 0 && t == 0) g_rowoff[NN] = EE;
}

__global__ void scatter_plain(const void* __restrict__ ei) {
    int i = blockIdx.x * blockDim.x + threadIdx.x;
    if (i >= EE) return;
    int s = edge_at(ei, i);
    int d = edge_at(ei, EE + i);
    int pos = atomicAdd(&g_cursor[d], 1);
    g_csrc[pos] = s;
}

// ------------------------- gather (layer 1), single pass -------------------
__global__ __launch_bounds__(256) void gather1_kernel() {
    int warp = (blockIdx.x * blockDim.x + threadIdx.x) >> 5;
    int lane = threadIdx.x & 31;
    if (warp >= NN) return;
    int dst = warp;
    int beg = g_rowoff[dst];
    int end = g_rowoff[dst + 1];
    float er = g_er1[dst];

    float4 acc = make_float4(0.f, 0.f, 0.f, 0.f);
    float dsum = 0.f;
    for (int j0 = beg; j0 < end; j0 += 32) {
        int jj = j0 + lane;
        int s_l = 0;
        float w_l = 0.f;
        if (jj < end) {
            s_l = g_csrc[jj];
            w_l = expf(leaky(g_el1[s_l] + er));
        }
        int cnt = min(32, end - j0);
        for (int u = 0; u < cnt; u++) {
            float a = __shfl_sync(0xffffffffu, w_l, u);
            int s = __shfl_sync(0xffffffffu, s_l, u);
            float4 v = *(const float4*)&g_xl1[(size_t)s * HID + lane * 4];
            acc.x += a * v.x; acc.y += a * v.y; acc.z += a * v.z; acc.w += a * v.w;
            dsum += a;
        }
    }
    float inv = __fdividef(1.f, dsum + 1e-16f);
    acc.x *= inv; acc.y *= inv; acc.z *= inv; acc.w *= inv;
    *(float4*)&g_agg1[(size_t)dst * HID + lane * 4] = acc;
}

// ------------------------- layer-2 GEMM ------------------------------------
__global__ __launch_bounds__(128) void gemm2_kernel(const float* __restrict__ b1) {
    __shared__ float Ws[HID * 24];
    __shared__ float Hs[128][33];
    int tid = threadIdx.x;
    for (int i = tid; i < HID * 24; i += 128) Ws[i] = g_Wt2[i];
    int rt = tid >> 3;
    int ct = tid & 7;
    int rowBase = blockIdx.x * 128;
    float acc[8][3] = {};

    for (int k0 = 0; k0 < HID; k0 += 32) {
        __syncthreads();
#pragma unroll
        for (int l = 0; l < 8; l++) {
            int idx = tid + l * 128;
            int r = idx >> 3;
            int kc = idx & 7;
            int row = rowBase + r;
            float4 v = make_float4(0.f, 0.f, 0.f, 0.f);
            if (row < NN) v = *(const float4*)&g_agg1[(size_t)row * HID + k0 + kc * 4];
            int kb = k0 + kc * 4;
            Hs[r][kc * 4 + 0] = eluf(v.x + b1[kb + 0]);
            Hs[r][kc * 4 + 1] = eluf(v.y + b1[kb + 1]);
            Hs[r][kc * 4 + 2] = eluf(v.z + b1[kb + 2]);
            Hs[r][kc * 4 + 3] = eluf(v.w + b1[kb + 3]);
        }
        __syncthreads();
#pragma unroll
        for (int kk = 0; kk < 32; kk++) {
            float w0 = Ws[(k0 + kk) * 24 + ct * 3 + 0];
            float w1 = Ws[(k0 + kk) * 24 + ct * 3 + 1];
            float w2 = Ws[(k0 + kk) * 24 + ct * 3 + 2];
#pragma unroll
            for (int i = 0; i < 8; i++) {
                float a = Hs[rt * 8 + i][kk];
                acc[i][0] += a * w0;
                acc[i][1] += a * w1;
                acc[i][2] += a * w2;
            }
        }
    }
#pragma unroll
    for (int i = 0; i < 8; i++) {
        int row = rowBase + rt * 8 + i;
        if (row < NN) {
#pragma unroll
            for (int j = 0; j < 3; j++) {
                int c = ct * 3 + j;
                float vv = acc[i][j];
                if (c < DOUT) {
                    g_xl2[row * DOUT + c] = vv;
                } else if (c == 20) {
                    g_el2[row] = vv;
                } else if (c == 21) {
                    g_er2[row] = vv;
                }
            }
        }
    }
}

// ------------------- gather (layer 2) single pass + final combine ----------
__global__ __launch_bounds__(256) void gather2_kernel(const float* __restrict__ b0,
                                                      const float* __restrict__ b2,
                                                      float* __restrict__ out) {
    int warp = (blockIdx.x * blockDim.x + threadIdx.x) >> 5;
    int lane = threadIdx.x & 31;
    if (warp >= NN) return;
    int dst = warp;
    int beg = g_rowoff[dst];
    int end = g_rowoff[dst + 1];
    float er = g_er2[dst];

    float acc = 0.f;
    float dsum = 0.f;
    for (int j0 = beg; j0 < end; j0 += 32) {
        int jj = j0 + lane;
        int s_l = 0;
        float w_l = 0.f;
        if (jj < end) {
            s_l = g_csrc[jj];
            w_l = expf(leaky(g_el2[s_l] + er));
        }
        int cnt = min(32, end - j0);
        for (int u = 0; u < cnt; u++) {
            float a = __shfl_sync(0xffffffffu, w_l, u);
            int s = __shfl_sync(0xffffffffu, s_l, u);
            if (lane < DOUT) acc += a * g_xl2[(size_t)s * DOUT + lane];
            dsum += a;
        }
    }
    float inv = __fdividef(1.f, dsum + 1e-16f);
    acc *= inv;

    float ev = 0.f;
    if (lane < DOUT) ev = expf(acc + b2[lane]);
    float rs = ev;
#pragma unroll
    for (int off = 16; off; off >>= 1)
        rs += __shfl_xor_sync(0xffffffffu, rs, off);
    float ir = __fdividef(1.f, rs);
    if (lane < DOUT) {
        float p0 = expf(g_s0[dst * DOUT + lane] + b0[lane]) *
                   __fdividef(1.f, g_colsum0[lane]);
        out[dst * DOUT + lane] = p0 * ev * ir;
    }
}

// ------------------------- launch ------------------------------------------
extern "C" void kernel_launch(void* const* d_in, const int* in_sizes, int n_in,
                              void* d_out, int out_size) {
    const float* x        = (const float*)d_in[0];
    const void* ei        = d_in[1];
    const float* W0       = (const float*)d_in[2];
    const float* b0       = (const float*)d_in[3];
    const float* g1Wl     = (const float*)d_in[4];
    const float* g1Wr     = (const float*)d_in[5];
    const float* g1al     = (const float*)d_in[6];
    const float* g1ar     = (const float*)d_in[7];
    const float* g1b      = (const float*)d_in[8];
    const float* g2Wl     = (const float*)d_in[9];
    const float* g2Wr     = (const float*)d_in[10];
    const float* g2al     = (const float*)d_in[11];
    const float* g2ar     = (const float*)d_in[12];
    const float* g2b      = (const float*)d_in[13];
    float* out            = (float*)d_out;

    cudaFuncSetAttribute(gemm_mma, cudaFuncAttributeMaxDynamicSharedMemorySize, SMEM_SZ);

    cudaStream_t s2;
    cudaEvent_t evFork, evJoin, evGemm, evCol;
    cudaStreamCreateWithFlags(&s2, cudaStreamNonBlocking);
    cudaEventCreateWithFlags(&evFork, cudaEventDisableTiming);
    cudaEventCreateWithFlags(&evJoin, cudaEventDisableTiming);
    cudaEventCreateWithFlags(&evGemm, cudaEventDisableTiming);
    cudaEventCreateWithFlags(&evCol, cudaEventDisableTiming);

    // fork immediately: side branch owns detect + CSR build
    cudaEventRecord(evFork, 0);
    cudaStreamWaitEvent(s2, evFork, 0);
    detect_kernel<<<NB_SCAN, 512, 0, s2>>>(ei);
    deg_count<<<(EE + 255) / 256, 256, 0, s2>>>(ei);
    scanA_kernel<<<NB_SCAN, 512, 0, s2>>>();
    scanB_kernel<<<1, 128, 0, s2>>>();
    scanC_kernel<<<NB_SCAN, 512, 0, s2>>>();
    scatter_plain<<<(EE + 255) / 256, 256, 0, s2>>>(ei);
    cudaEventRecord(evJoin, s2);

    // main branch: prep (builds fragments directly) + big GEMM
    prep_kernel<<<161, 512>>>(W0, g1Wl, g1Wr, g1al, g1ar, g2Wl, g2Wr, g2al, g2ar);
    gemm_mma<<<(NN + 127) / 128, 512, SMEM_SZ>>>(x);
    cudaEventRecord(evGemm, 0);

    // colsum on side stream, overlapped with gather1/gemm2 (only gather2 needs it)
    cudaStreamWaitEvent(s2, evGemm, 0);
    colsum_kernel<<<400, 256, 0, s2>>>(b0);
    cudaEventRecord(evCol, s2);

    cudaStreamWaitEvent(0, evJoin, 0);
    gather1_kernel<<<(NN * 32 + 255) / 256, 256>>>();
    gemm2_kernel<<<(NN + 127) / 128, 128>>>(g1b);
    cudaStreamWaitEvent(0, evCol, 0);
    gather2_kernel<<<(NN * 32 + 255) / 256, 256>>>(b0, g2b, out);

    cudaEventDestroy(evFork);
    cudaEventDestroy(evJoin);
    cudaEventDestroy(evGemm);
    cudaEventDestroy(evCol);
    cudaStreamDestroy(s2);
}

// round 16
// speedup vs baseline: 1.0454x; 1.0454x over previous
#include <cuda_runtime.h>
#include <cuda_bf16.h>
#include <math.h>
#include <stdint.h>

// ---------------------------------------------------------------------------
// GAT pipeline (R14 config restored: gemm BM=64/256thr/2CTA-SM — fastest
// measured; BM=128 experiment regressed and is abandoned).
// Big GEMM: mma.sync bf16 split-precision, cp.async double-buffered B +
// register-prefetched A. CSR build on forked stream. Single-pass gathers
// (with unroll-4 broadcast loops). Colsum overlapped on side stream.
// ---------------------------------------------------------------------------

#define NN   50000
#define EE   500000
#define KDIM 512
#define HID  128
#define DOUT 20
#define NB_SCAN 98            // ceil(NN/512)

#define NSTEPS 32             // 512 / 16 k-steps
#define NTILES 20             // 160 / 8 n-tiles
#define BFRAG_CNT (NSTEPS * NTILES * 32)   // B fragment table entries (uint4)

// gemm tiling: BM=64, BN=160, chunk K=64 (4 k-steps), 256 threads = 8 warps
#define CH_STEPS 4
#define NCHUNKS 8
// smem layout (bytes)
#define OFF_AF_H 0
#define OFF_AF_L 8192
#define OFF_B0   16384
#define OFF_B1   (OFF_B0 + 40960)
#define SMEM_SZ  (OFF_B1 + 40960)          // 98304

// ------------------------- device scratch ---------------------------------
__device__ __align__(16) float g_Wt2[HID * 24];     // layer-2 B, [k][c]
__device__ __align__(16) uint4 g_Bf[BFRAG_CNT];     // B fragments {bh.xy, bl.xy}
__device__ __align__(16) float g_xl1[NN * HID];
__device__ __align__(16) float g_agg1[NN * HID];
__device__ __align__(16) float g_s0[NN * DOUT];
__device__ float g_el1[NN], g_er1[NN];
__device__ __align__(16) float g_xl2[NN * DOUT];
__device__ float g_el2[NN], g_er2[NN];
__device__ float g_colsum0[DOUT];
__device__ int g_is64;
// CSR
__device__ int g_deg[NN];
__device__ int g_rowoff[NN + 1];
__device__ int g_cursor[NN];
__device__ int g_bsum[NB_SCAN];
__device__ int g_boff[NB_SCAN];
__device__ int g_csrc[EE];

// ------------------------- helpers ----------------------------------------
__device__ __forceinline__ float eluf(float x) {
    return x > 0.f ? x : expm1f(x);
}
__device__ __forceinline__ float leaky(float x) {
    return x > 0.f ? x : 0.2f * x;
}
__device__ __forceinline__ uint32_t packbf(float a, float b) {
    uint32_t r;
    asm("cvt.rn.bf16x2.f32 %0, %1, %2;" : "=r"(r) : "f"(b), "f"(a));
    return r;
}
__device__ __forceinline__ float bflo(float v) {
    __nv_bfloat16 h = __float2bfloat16(v);
    return v - __bfloat162float(h);
}
__device__ __forceinline__ uint32_t smem_u32(const void* p) {
    uint32_t a;
    asm("{ .reg .u64 t; cvta.to.shared.u64 t, %1; cvt.u32.u64 %0, t; }"
        : "=r"(a) : "l"(p));
    return a;
}
__device__ __forceinline__ void cp_async16(uint32_t saddr, const void* g) {
    asm volatile(
        "{ .reg .u64 t; cvta.to.global.u64 t, %1;"
        "  cp.async.cg.shared.global [%0], [t], 16; }"
        :: "r"(saddr), "l"(g) : "memory");
}
__device__ __forceinline__ void mma_bf16(float& c0, float& c1, float& c2, float& c3,
                                         uint32_t a0, uint32_t a1, uint32_t a2, uint32_t a3,
                                         uint32_t b0, uint32_t b1) {
    asm volatile(
        "mma.sync.aligned.m16n8k16.row.col.f32.bf16.bf16.f32 "
        "{%0,%1,%2,%3}, {%4,%5,%6,%7}, {%8,%9}, {%0,%1,%2,%3};"
        : "+f"(c0), "+f"(c1), "+f"(c2), "+f"(c3)
        : "r"(a0), "r"(a1), "r"(a2), "r"(a3), "r"(b0), "r"(b1));
}

// ------------------------- dtype detection + deg zero (side stream) --------
__global__ void detect_kernel(const void* ei) {
    int i = blockIdx.x * blockDim.x + threadIdx.x;
    if (i < NN) g_deg[i] = 0;
    if (i == 0) {
        const long long* p = (const long long*)ei;
        int ok64 = 1;
        for (int k = 0; k < 64; k++) {
            long long v = p[k];
            if (v < 0 || v >= NN) { ok64 = 0; break; }
        }
        g_is64 = ok64;
    }
}
__device__ __forceinline__ int edge_at(const void* ei, int idx) {
    if (g_is64) return (int)((const long long*)ei)[idx];
    return ((const int*)ei)[idx];
}

// ------------------------- prep (fused fragment build) ---------------------
__global__ void prep_kernel(const float* __restrict__ W0,
                            const float* __restrict__ Wl1, const float* __restrict__ Wr1,
                            const float* __restrict__ al1, const float* __restrict__ ar1,
                            const float* __restrict__ Wl2, const float* __restrict__ Wr2,
                            const float* __restrict__ al2, const float* __restrict__ ar2) {
    __shared__ float col[KDIM];
    int b = blockIdx.x;
    int t = threadIdx.x;  // 0..511

    if (b < 160) {
        float v;
        if (b < 128) {
            v = Wl1[b * KDIM + t];
        } else if (b < 148) {
            v = W0[(b - 128) * KDIM + t];
        } else if (b == 148) {
            float s = 0.f;
            for (int h = 0; h < HID; h++) s += Wl1[h * KDIM + t] * al1[h];
            v = s;
        } else if (b == 149) {
            float s = 0.f;
            for (int h = 0; h < HID; h++) s += Wr1[h * KDIM + t] * ar1[h];
            v = s;
        } else {
            v = 0.f;
        }
        col[t] = v;
        __syncthreads();
        if (t < 128) {
            int s = t >> 2;          // k-step 0..31
            int q = t & 3;
            int k = s * 16 + 2 * q;
            float v0 = col[k];
            float v1 = col[k + 1];
            float v2 = col[k + 8];
            float v3 = col[k + 9];
            int tile = b >> 3;
            int lane = ((b & 7) << 2) | q;
            int f = (s * NTILES + tile) * 32 + lane;
            g_Bf[f] = make_uint4(packbf(v0, v1), packbf(v2, v3),
                                 packbf(bflo(v0), bflo(v1)), packbf(bflo(v2), bflo(v3)));
        }
    } else {
        if (t < HID) {
            for (int c = 0; c < DOUT; c++) g_Wt2[t * 24 + c] = Wl2[c * HID + t];
            float s = 0.f;
            for (int h = 0; h < DOUT; h++) s += Wl2[h * HID + t] * al2[h];
            g_Wt2[t * 24 + 20] = s;
            s = 0.f;
            for (int h = 0; h < DOUT; h++) s += Wr2[h * HID + t] * ar2[h];
            g_Wt2[t * 24 + 21] = s;
            g_Wt2[t * 24 + 22] = 0.f;
            g_Wt2[t * 24 + 23] = 0.f;
        } else if (t < 128 + DOUT) {
            g_colsum0[t - 128] = 0.f;
        }
    }
}

// ------------------------- mma.sync big GEMM (R14: BM=64, 256 thr) ---------
__global__ void __launch_bounds__(256, 2) gemm_mma(const float* __restrict__ x) {
    extern __shared__ __align__(16) char sm[];
    uint32_t sb = smem_u32(sm);
    int tid = threadIdx.x;
    int wid = tid >> 5;
    int lane = tid & 31;
    int mw = wid >> 2;
    int nw = wid & 3;
    int g = lane >> 2, q = lane & 3;
    int rowBase = blockIdx.x * 64;

    int rA[4]; int c4A[4]; bool okA[4];
#pragma unroll
    for (int i = 0; i < 4; i++) {
        int idx = tid + i * 256;
        rA[i] = idx >> 4;
        c4A[i] = idx & 15;
        okA[i] = (rowBase + rA[i]) < NN;
    }

    float acc[2][5][4];
#pragma unroll
    for (int i = 0; i < 2; i++)
#pragma unroll
        for (int j = 0; j < 5; j++)
#pragma unroll
            for (int k = 0; k < 4; k++) acc[i][j][k] = 0.f;

    float4 areg[4];
#pragma unroll
    for (int i = 0; i < 4; i++) {
        areg[i] = make_float4(0.f, 0.f, 0.f, 0.f);
        if (okA[i])
            areg[i] = *(const float4*)(x + (size_t)(rowBase + rA[i]) * KDIM + c4A[i] * 4);
    }
#pragma unroll
    for (int i = 0; i < 10; i++) {
        int s = tid + i * 256;
        cp_async16(sb + OFF_B0 + s * 16, g_Bf + s);
    }
    asm volatile("cp.async.commit_group;" ::: "memory");

    for (int ch = 0; ch < NCHUNKS; ch++) {
#pragma unroll
        for (int i = 0; i < 4; i++) {
            float4 v = areg[i];
            uint32_t h0 = packbf(v.x, v.y);
            uint32_t h1 = packbf(v.z, v.w);
            uint32_t l0 = packbf(bflo(v.x), bflo(v.y));
            uint32_t l1 = packbf(bflo(v.z), bflo(v.w));
            int r = rA[i];
            int p0 = 2 * c4A[i];
            int s = p0 >> 3;
            int j = (((p0 >> 2) & 1) << 1) | ((r >> 3) & 1);
            int lane0 = ((r & 7) << 2) | (p0 & 3);
            int mt = r >> 4;
            int base = ((s * 4 + mt) * 32) * 16 + j * 4;
            *(uint32_t*)(sm + OFF_AF_H + base + lane0 * 16) = h0;
            *(uint32_t*)(sm + OFF_AF_H + base + (lane0 + 1) * 16) = h1;
            *(uint32_t*)(sm + OFF_AF_L + base + lane0 * 16) = l0;
            *(uint32_t*)(sm + OFF_AF_L + base + (lane0 + 1) * 16) = l1;
        }
        float4 anext[4];
#pragma unroll
        for (int i = 0; i < 4; i++) anext[i] = make_float4(0.f, 0.f, 0.f, 0.f);
        if (ch < NCHUNKS - 1) {
            int k0n = (ch + 1) * 64;
#pragma unroll
            for (int i = 0; i < 4; i++) {
                if (okA[i])
                    anext[i] = *(const float4*)(x + (size_t)(rowBase + rA[i]) * KDIM
                                                + k0n + c4A[i] * 4);
            }
            uint32_t dstB = sb + (((ch + 1) & 1) ? OFF_B1 : OFF_B0);
            const uint4* srcB = g_Bf + (ch + 1) * (CH_STEPS * NTILES * 32);
#pragma unroll
            for (int i = 0; i < 10; i++) {
                int s = tid + i * 256;
                cp_async16(dstB + s * 16, srcB + s);
            }
            asm volatile("cp.async.commit_group;" ::: "memory");
            asm volatile("cp.async.wait_group 1;" ::: "memory");
        } else {
            asm volatile("cp.async.wait_group 0;" ::: "memory");
        }
        __syncthreads();

        int offB = (ch & 1) ? OFF_B1 : OFF_B0;
#pragma unroll
        for (int s = 0; s < CH_STEPS; s++) {
            uint4 ah[2], al[2];
#pragma unroll
            for (int mt = 0; mt < 2; mt++) {
                int tile = s * 4 + mw * 2 + mt;
                ah[mt] = *(uint4*)(sm + OFF_AF_H + (tile * 32 + lane) * 16);
                al[mt] = *(uint4*)(sm + OFF_AF_L + (tile * 32 + lane) * 16);
            }
#pragma unroll
            for (int nt = 0; nt < 5; nt++) {
                int fi = (s * NTILES + nw * 5 + nt) * 32 + lane;
                uint4 bb = *(uint4*)(sm + offB + fi * 16);
#pragma unroll
                for (int mt = 0; mt < 2; mt++) {
                    mma_bf16(acc[mt][nt][0], acc[mt][nt][1], acc[mt][nt][2], acc[mt][nt][3],
                             ah[mt].x, ah[mt].y, ah[mt].z, ah[mt].w, bb.x, bb.y);
                    mma_bf16(acc[mt][nt][0], acc[mt][nt][1], acc[mt][nt][2], acc[mt][nt][3],
                             ah[mt].x, ah[mt].y, ah[mt].z, ah[mt].w, bb.z, bb.w);
                    mma_bf16(acc[mt][nt][0], acc[mt][nt][1], acc[mt][nt][2], acc[mt][nt][3],
                             al[mt].x, al[mt].y, al[mt].z, al[mt].w, bb.x, bb.y);
                }
            }
        }
        __syncthreads();
#pragma unroll
        for (int i = 0; i < 4; i++) areg[i] = anext[i];
    }

#pragma unroll
    for (int mt = 0; mt < 2; mt++) {
#pragma unroll
        for (int half = 0; half < 2; half++) {
            int row = rowBase + (mw * 2 + mt) * 16 + half * 8 + g;
            if (row >= NN) continue;
#pragma unroll
            for (int nt = 0; nt < 5; nt++) {
                int col = nw * 40 + nt * 8 + 2 * q;
                float c0 = acc[mt][nt][half * 2 + 0];
                float c1 = acc[mt][nt][half * 2 + 1];
                if (col < HID) {
                    *(float2*)&g_xl1[(size_t)row * HID + col] = make_float2(c0, c1);
                } else {
                    int cc = col - HID;
                    if (cc < DOUT) {
                        *(float2*)&g_s0[(size_t)row * DOUT + cc] = make_float2(c0, c1);
                    } else if (cc == DOUT) {
                        g_el1[row] = c0;
                        g_er1[row] = c1;
                    }
                }
            }
        }
    }
}

// ------------------------- column-softmax reduce ---------------------------
__global__ void colsum_kernel(const float* __restrict__ b0) {
    __shared__ float bs[DOUT];
    int tid = threadIdx.x;
    if (tid < DOUT) bs[tid] = 0.f;
    __syncthreads();
    float ls[DOUT];
#pragma unroll
    for (int c = 0; c < DOUT; c++) ls[c] = 0.f;
    for (int n = blockIdx.x * blockDim.x + tid; n < NN; n += gridDim.x * blockDim.x) {
#pragma unroll
        for (int c = 0; c < DOUT; c++) ls[c] += expf(g_s0[n * DOUT + c] + b0[c]);
    }
#pragma unroll
    for (int c = 0; c < DOUT; c++) {
#pragma unroll
        for (int off = 16; off; off >>= 1)
            ls[c] += __shfl_xor_sync(0xffffffffu, ls[c], off);
    }
    if ((tid & 31) == 0) {
#pragma unroll
        for (int c = 0; c < DOUT; c++) atomicAdd(&bs[c], ls[c]);
    }
    __syncthreads();
    if (tid < DOUT) atomicAdd(&g_colsum0[tid], bs[tid]);
}

// ------------------------- CSR build (side stream) -------------------------
__global__ void deg_count(const void* __restrict__ ei) {
    int i = blockIdx.x * blockDim.x + threadIdx.x;
    if (i >= EE) return;
    int d = edge_at(ei, EE + i);
    atomicAdd(&g_deg[d], 1);
}

__global__ void scanA_kernel() {
    __shared__ int warpsum[16];
    int b = blockIdx.x, t = threadIdx.x;
    int i = b * 512 + t;
    int v = (i < NN) ? g_deg[i] : 0;
    int x = v;
#pragma unroll
    for (int off = 1; off < 32; off <<= 1) {
        int y = __shfl_up_sync(0xffffffffu, x, off);
        if ((t & 31) >= off) x += y;
    }
    if ((t & 31) == 31) warpsum[t >> 5] = x;
    __syncthreads();
    if (t < 16) {
        int s = warpsum[t];
#pragma unroll
        for (int off = 1; off < 16; off <<= 1) {
            int y = __shfl_up_sync(0xffffu, s, off);
            if (t >= off) s += y;
        }
        warpsum[t] = s;
    }
    __syncthreads();
    int incl = x + ((t >> 5) ? warpsum[(t >> 5) - 1] : 0);
    if (i < NN) g_rowoff[i] = incl - v;
    if (t == 511) g_bsum[b] = incl;
}

__global__ void scanB_kernel() {
    __shared__ int warpsum[4];
    int t = threadIdx.x;
    int v = (t < NB_SCAN) ? g_bsum[t] : 0;
    int x = v;
#pragma unroll
    for (int off = 1; off < 32; off <<= 1) {
        int y = __shfl_up_sync(0xffffffffu, x, off);
        if ((t & 31) >= off) x += y;
    }
    if ((t & 31) == 31) warpsum[t >> 5] = x;
    __syncthreads();
    if (t < 4) {
        int s = warpsum[t];
#pragma unroll
        for (int off = 1; off < 4; off <<= 1) {
            int y = __shfl_up_sync(0xfu, s, off);
            if (t >= off) s += y;
        }
        warpsum[t] = s;
    }
    __syncthreads();
    int incl = x + ((t >> 5) ? warpsum[(t >> 5) - 1] : 0);
    if (t < NB_SCAN) g_boff[t] = incl - v;
}

__global__ void scanC_kernel() {
    int b = blockIdx.x, t = threadIdx.x;
    int i = b * 512 + t;
    if (i < NN) {
        int o = g_rowoff[i] + g_boff[b];
        g_rowoff[i] = o;
        g_cursor[i] = o;
    }
    if (b == 0 && t == 0) g_rowoff[NN] = EE;
}

__global__ void scatter_plain(const void* __restrict__ ei) {
    int i = blockIdx.x * blockDim.x + threadIdx.x;
    if (i >= EE) return;
    int s = edge_at(ei, i);
    int d = edge_at(ei, EE + i);
    int pos = atomicAdd(&g_cursor[d], 1);
    g_csrc[pos] = s;
}

// ------------------------- gather (layer 1), single pass -------------------
__global__ __launch_bounds__(256) void gather1_kernel() {
    int warp = (blockIdx.x * blockDim.x + threadIdx.x) >> 5;
    int lane = threadIdx.x & 31;
    if (warp >= NN) return;
    int dst = warp;
    int beg = g_rowoff[dst];
    int end = g_rowoff[dst + 1];
    float er = g_er1[dst];

    float4 acc = make_float4(0.f, 0.f, 0.f, 0.f);
    float dsum = 0.f;
    for (int j0 = beg; j0 < end; j0 += 32) {
        int jj = j0 + lane;
        int s_l = 0;
        float w_l = 0.f;
        if (jj < end) {
            s_l = g_csrc[jj];
            w_l = expf(leaky(g_el1[s_l] + er));
        }
        int cnt = min(32, end - j0);
#pragma unroll 4
        for (int u = 0; u < cnt; u++) {
            float a = __shfl_sync(0xffffffffu, w_l, u);
            int s = __shfl_sync(0xffffffffu, s_l, u);
            float4 v = *(const float4*)&g_xl1[(size_t)s * HID + lane * 4];
            acc.x += a * v.x; acc.y += a * v.y; acc.z += a * v.z; acc.w += a * v.w;
            dsum += a;
        }
    }
    float inv = __fdividef(1.f, dsum + 1e-16f);
    acc.x *= inv; acc.y *= inv; acc.z *= inv; acc.w *= inv;
    *(float4*)&g_agg1[(size_t)dst * HID + lane * 4] = acc;
}

// ------------------------- layer-2 GEMM ------------------------------------
__global__ __launch_bounds__(128) void gemm2_kernel(const float* __restrict__ b1) {
    __shared__ float Ws[HID * 24];
    __shared__ float Hs[128][33];
    int tid = threadIdx.x;
    for (int i = tid; i < HID * 24; i += 128) Ws[i] = g_Wt2[i];
    int rt = tid >> 3;
    int ct = tid & 7;
    int rowBase = blockIdx.x * 128;
    float acc[8][3] = {};

    for (int k0 = 0; k0 < HID; k0 += 32) {
        __syncthreads();
#pragma unroll
        for (int l = 0; l < 8; l++) {
            int idx = tid + l * 128;
            int r = idx >> 3;
            int kc = idx & 7;
            int row = rowBase + r;
            float4 v = make_float4(0.f, 0.f, 0.f, 0.f);
            if (row < NN) v = *(const float4*)&g_agg1[(size_t)row * HID + k0 + kc * 4];
            int kb = k0 + kc * 4;
            Hs[r][kc * 4 + 0] = eluf(v.x + b1[kb + 0]);
            Hs[r][kc * 4 + 1] = eluf(v.y + b1[kb + 1]);
            Hs[r][kc * 4 + 2] = eluf(v.z + b1[kb + 2]);
            Hs[r][kc * 4 + 3] = eluf(v.w + b1[kb + 3]);
        }
        __syncthreads();
#pragma unroll
        for (int kk = 0; kk < 32; kk++) {
            float w0 = Ws[(k0 + kk) * 24 + ct * 3 + 0];
            float w1 = Ws[(k0 + kk) * 24 + ct * 3 + 1];
            float w2 = Ws[(k0 + kk) * 24 + ct * 3 + 2];
#pragma unroll
            for (int i = 0; i < 8; i++) {
                float a = Hs[rt * 8 + i][kk];
                acc[i][0] += a * w0;
                acc[i][1] += a * w1;
                acc[i][2] += a * w2;
            }
        }
    }
#pragma unroll
    for (int i = 0; i < 8; i++) {
        int row = rowBase + rt * 8 + i;
        if (row < NN) {
#pragma unroll
            for (int j = 0; j < 3; j++) {
                int c = ct * 3 + j;
                float vv = acc[i][j];
                if (c < DOUT) {
                    g_xl2[row * DOUT + c] = vv;
                } else if (c == 20) {
                    g_el2[row] = vv;
                } else if (c == 21) {
                    g_er2[row] = vv;
                }
            }
        }
    }
}

// ------------------- gather (layer 2) single pass + final combine ----------
__global__ __launch_bounds__(256) void gather2_kernel(const float* __restrict__ b0,
                                                      const float* __restrict__ b2,
                                                      float* __restrict__ out) {
    int warp = (blockIdx.x * blockDim.x + threadIdx.x) >> 5;
    int lane = threadIdx.x & 31;
    if (warp >= NN) return;
    int dst = warp;
    int beg = g_rowoff[dst];
    int end = g_rowoff[dst + 1];
    float er = g_er2[dst];

    float acc = 0.f;
    float dsum = 0.f;
    for (int j0 = beg; j0 < end; j0 += 32) {
        int jj = j0 + lane;
        int s_l = 0;
        float w_l = 0.f;
        if (jj < end) {
            s_l = g_csrc[jj];
            w_l = expf(leaky(g_el2[s_l] + er));
        }
        int cnt = min(32, end - j0);
#pragma unroll 4
        for (int u = 0; u < cnt; u++) {
            float a = __shfl_sync(0xffffffffu, w_l, u);
            int s = __shfl_sync(0xffffffffu, s_l, u);
            if (lane < DOUT) acc += a * g_xl2[(size_t)s * DOUT + lane];
            dsum += a;
        }
    }
    float inv = __fdividef(1.f, dsum + 1e-16f);
    acc *= inv;

    float ev = 0.f;
    if (lane < DOUT) ev = expf(acc + b2[lane]);
    float rs = ev;
#pragma unroll
    for (int off = 16; off; off >>= 1)
        rs += __shfl_xor_sync(0xffffffffu, rs, off);
    float ir = __fdividef(1.f, rs);
    if (lane < DOUT) {
        float p0 = expf(g_s0[dst * DOUT + lane] + b0[lane]) *
                   __fdividef(1.f, g_colsum0[lane]);
        out[dst * DOUT + lane] = p0 * ev * ir;
    }
}

// ------------------------- launch ------------------------------------------
extern "C" void kernel_launch(void* const* d_in, const int* in_sizes, int n_in,
                              void* d_out, int out_size) {
    const float* x        = (const float*)d_in[0];
    const void* ei        = d_in[1];
    const float* W0       = (const float*)d_in[2];
    const float* b0       = (const float*)d_in[3];
    const float* g1Wl     = (const float*)d_in[4];
    const float* g1Wr     = (const float*)d_in[5];
    const float* g1al     = (const float*)d_in[6];
    const float* g1ar     = (const float*)d_in[7];
    const float* g1b      = (const float*)d_in[8];
    const float* g2Wl     = (const float*)d_in[9];
    const float* g2Wr     = (const float*)d_in[10];
    const float* g2al     = (const float*)d_in[11];
    const float* g2ar     = (const float*)d_in[12];
    const float* g2b      = (const float*)d_in[13];
    float* out            = (float*)d_out;

    cudaFuncSetAttribute(gemm_mma, cudaFuncAttributeMaxDynamicSharedMemorySize, SMEM_SZ);

    cudaStream_t s2;
    cudaEvent_t evFork, evJoin, evGemm, evCol;
    cudaStreamCreateWithFlags(&s2, cudaStreamNonBlocking);
    cudaEventCreateWithFlags(&evFork, cudaEventDisableTiming);
    cudaEventCreateWithFlags(&evJoin, cudaEventDisableTiming);
    cudaEventCreateWithFlags(&evGemm, cudaEventDisableTiming);
    cudaEventCreateWithFlags(&evCol, cudaEventDisableTiming);

    // fork immediately: side branch owns detect + CSR build
    cudaEventRecord(evFork, 0);
    cudaStreamWaitEvent(s2, evFork, 0);
    detect_kernel<<<NB_SCAN, 512, 0, s2>>>(ei);
    deg_count<<<(EE + 255) / 256, 256, 0, s2>>>(ei);
    scanA_kernel<<<NB_SCAN, 512, 0, s2>>>();
    scanB_kernel<<<1, 128, 0, s2>>>();
    scanC_kernel<<<NB_SCAN, 512, 0, s2>>>();
    scatter_plain<<<(EE + 255) / 256, 256, 0, s2>>>(ei);
    cudaEventRecord(evJoin, s2);

    // main branch: prep (builds fragments directly) + big GEMM
    prep_kernel<<<161, 512>>>(W0, g1Wl, g1Wr, g1al, g1ar, g2Wl, g2Wr, g2al, g2ar);
    gemm_mma<<<(NN + 63) / 64, 256, SMEM_SZ>>>(x);
    cudaEventRecord(evGemm, 0);

    // colsum on side stream, overlapped with gather1/gemm2 (only gather2 needs it)
    cudaStreamWaitEvent(s2, evGemm, 0);
    colsum_kernel<<<400, 256, 0, s2>>>(b0);
    cudaEventRecord(evCol, s2);

    cudaStreamWaitEvent(0, evJoin, 0);
    gather1_kernel<<<(NN * 32 + 255) / 256, 256>>>();
    gemm2_kernel<<<(NN + 127) / 128, 128>>>(g1b);
    cudaStreamWaitEvent(0, evCol, 0);
    gather2_kernel<<<(NN * 32 + 255) / 256, 256>>>(b0, g2b, out);

    cudaEventDestroy(evFork);
    cudaEventDestroy(evJoin);
    cudaEventDestroy(evGemm);
    cudaEventDestroy(evCol);
    cudaStreamDestroy(s2);
}